// round 4
// baseline (speedup 1.0000x reference)
#include <cuda_runtime.h>
#include <cstdint>
#include <cstddef>

namespace {
constexpr int B2  = 2;
constexpr int SEQ = 2048;
constexpr int DM  = 512;
constexpr int NH  = 8;
constexpr int DKH = 64;
constexpr int MM  = B2 * SEQ;              // 4096
constexpr float INV_TEMP = 0.04419417382415922f;  // 1/sqrt(512)
constexpr float LN_EPS = 1e-5f;
}

// Scratch (device globals — allocations are forbidden)
__device__ float g_Q[MM * DM];
__device__ float g_K[MM * DM];
__device__ float g_V[MM * DM];
__device__ float g_ctx[MM * DM];
__device__ float g_x[MM * DM];

__device__ __forceinline__ float tf32r(float x) {
  uint32_t o;
  asm("cvt.rna.tf32.f32 %0, %1;" : "=r"(o) : "f"(x));
  return __uint_as_float(o);
}

__device__ __forceinline__ void mma8(float* c, const uint32_t* a, const uint32_t* b) {
  asm volatile(
      "mma.sync.aligned.m16n8k8.row.col.f32.tf32.tf32.f32 "
      "{%0,%1,%2,%3}, {%4,%5,%6,%7}, {%8,%9}, {%0,%1,%2,%3};"
      : "+f"(c[0]), "+f"(c[1]), "+f"(c[2]), "+f"(c[3])
      : "r"(a[0]), "r"(a[1]), "r"(a[2]), "r"(a[3]), "r"(b[0]), "r"(b[1]));
}

// ---------------------------------------------------------------------------
// Dense GEMM, 1xTF32: out[m,n] = sum_k X[m,k]*W[n,k] + bias[n] (+resid)
// CTA 128x128, 8 warps (4m x 2n), warp 32x64 = mma 2m x 8n, K-step 16.
// smem stride 20; staging uses row=idx&127 so STS is conflict-free.
// ---------------------------------------------------------------------------
__global__ __launch_bounds__(256) void gemm_mma(
    const float* __restrict__ X, const float* __restrict__ W,
    const float* __restrict__ bias, const float* __restrict__ resid,
    float* __restrict__ out) {
  __shared__ float As[128][20];
  __shared__ float Bs[128][20];
  const int tid = threadIdx.x;
  const int lane = tid & 31, wid = tid >> 5;
  const int g = lane >> 2, tig = lane & 3;
  const int wm = wid & 3, wn = wid >> 2;       // 4m x 2n warps
  const int mbase = blockIdx.y << 7;
  const int nbase = blockIdx.x << 7;

  float c[2][8][4] = {};

  for (int kb = 0; kb < DM; kb += 16) {
#pragma unroll
    for (int j = 0; j < 2; j++) {
      int idx = tid + (j << 8);
      int row = idx & 127;
      int c4  = (idx >> 7) << 2;               // j=0: 0/4, j=1: 8/12
      float4 v = *reinterpret_cast<const float4*>(&X[(size_t)(mbase + row) * DM + kb + c4]);
      v.x = tf32r(v.x); v.y = tf32r(v.y); v.z = tf32r(v.z); v.w = tf32r(v.w);
      *reinterpret_cast<float4*>(&As[row][c4]) = v;
      float4 w = *reinterpret_cast<const float4*>(&W[(size_t)(nbase + row) * DM + kb + c4]);
      w.x = tf32r(w.x); w.y = tf32r(w.y); w.z = tf32r(w.z); w.w = tf32r(w.w);
      *reinterpret_cast<float4*>(&Bs[row][c4]) = w;
    }
    __syncthreads();

#pragma unroll
    for (int kk = 0; kk < 16; kk += 8) {
      uint32_t a[2][4], b[8][2];
#pragma unroll
      for (int mt = 0; mt < 2; mt++) {
        int r = (wm << 5) + (mt << 4) + g;
        a[mt][0] = __float_as_uint(As[r][kk + tig]);
        a[mt][1] = __float_as_uint(As[r + 8][kk + tig]);
        a[mt][2] = __float_as_uint(As[r][kk + tig + 4]);
        a[mt][3] = __float_as_uint(As[r + 8][kk + tig + 4]);
      }
#pragma unroll
      for (int nt = 0; nt < 8; nt++) {
        int cc = (wn << 6) + (nt << 3) + g;
        b[nt][0] = __float_as_uint(Bs[cc][kk + tig]);
        b[nt][1] = __float_as_uint(Bs[cc][kk + tig + 4]);
      }
#pragma unroll
      for (int mt = 0; mt < 2; mt++)
#pragma unroll
        for (int nt = 0; nt < 8; nt++)
          mma8(c[mt][nt], a[mt], b[nt]);
    }
    __syncthreads();
  }

#pragma unroll
  for (int mt = 0; mt < 2; mt++) {
    int r = mbase + (wm << 5) + (mt << 4) + g;
#pragma unroll
    for (int nt = 0; nt < 8; nt++) {
      int cc = nbase + (wn << 6) + (nt << 3) + (tig << 1);
      float2 bv = *reinterpret_cast<const float2*>(&bias[cc]);
      float o0 = c[mt][nt][0] + bv.x, o1 = c[mt][nt][1] + bv.y;
      float o2 = c[mt][nt][2] + bv.x, o3 = c[mt][nt][3] + bv.y;
      if (resid != nullptr) {
        float2 r0 = *reinterpret_cast<const float2*>(&resid[(size_t)r * DM + cc]);
        float2 r1 = *reinterpret_cast<const float2*>(&resid[(size_t)(r + 8) * DM + cc]);
        o0 += r0.x; o1 += r0.y; o2 += r1.x; o3 += r1.y;
      }
      float2 w0 = {o0, o1}, w1 = {o2, o3};
      *reinterpret_cast<float2*>(&out[(size_t)r * DM + cc]) = w0;
      *reinterpret_cast<float2*>(&out[(size_t)(r + 8) * DM + cc]) = w1;
    }
  }
}

// ---------------------------------------------------------------------------
// Fused attention, TF32 mma, register-resident Q fragments.
// CTA = 128 q x one (b,h), 8 warps (4q x 2n), warp 32x32.
// smem (71168B): Qs/Es[128][68] | Ks[64][68] | Vt[64][68] | red[128][2] | sinv
// ---------------------------------------------------------------------------
__global__ __launch_bounds__(256, 1) void attn_mma(float* __restrict__ attn_out) {
  extern __shared__ float sm[];
  float (*Qs)[68] = reinterpret_cast<float(*)[68]>(sm);            // then Es
  float (*Es)[68] = reinterpret_cast<float(*)[68]>(sm);
  float (*Ks)[68] = reinterpret_cast<float(*)[68]>(sm + 8704);
  float (*Vt)[68] = reinterpret_cast<float(*)[68]>(sm + 13056);
  float (*red)[2] = reinterpret_cast<float(*)[2]>(sm + 17408);
  float* sinv = sm + 17664;

  const int tid = threadIdx.x;
  const int lane = tid & 31, wid = tid >> 5;
  const int g = lane >> 2, tig = lane & 3;
  const int wq = wid >> 1, wn = wid & 1;       // 4q x 2n warps
  const int bh = blockIdx.y;                   // h*2 + b
  const int h = bh >> 1, b = bh & 1;
  const int qbase = blockIdx.x << 7;

  const float* Qg = g_Q + (size_t)(b * SEQ + qbase) * DM + h * DKH;
  const float* Kg = g_K + (size_t)(b * SEQ) * DM + h * DKH;
  const float* Vg = g_V + (size_t)(b * SEQ) * DM + h * DKH;

  // Stage Q once, pull fragments into registers, then Qs smem becomes Es.
#pragma unroll
  for (int j = 0; j < 8; j++) {
    int idx = tid + (j << 8);
    int row = idx >> 4, c4 = (idx & 15) << 2;
    float4 v = *reinterpret_cast<const float4*>(&Qg[(size_t)row * DM + c4]);
    v.x = tf32r(v.x); v.y = tf32r(v.y); v.z = tf32r(v.z); v.w = tf32r(v.w);
    *reinterpret_cast<float4*>(&Qs[row][c4]) = v;
  }
  __syncthreads();

  uint32_t qa[8][2][4];   // [d8][mt][reg] — register-resident Q fragments
#pragma unroll
  for (int d8i = 0; d8i < 8; d8i++) {
    int d8 = d8i << 3;
#pragma unroll
    for (int mt = 0; mt < 2; mt++) {
      int r = (wq << 5) + (mt << 4) + g;
      qa[d8i][mt][0] = __float_as_uint(Qs[r][d8 + tig]);
      qa[d8i][mt][1] = __float_as_uint(Qs[r + 8][d8 + tig]);
      qa[d8i][mt][2] = __float_as_uint(Qs[r][d8 + tig + 4]);
      qa[d8i][mt][3] = __float_as_uint(Qs[r + 8][d8 + tig + 4]);
    }
  }
  __syncthreads();

  // ---------------- sweep 1: rowsums ----------------
  float rs[2][2] = {};
  for (int kb = 0; kb < SEQ; kb += 64) {
#pragma unroll
    for (int j = 0; j < 4; j++) {
      int idx = tid + (j << 8);
      int row = idx >> 4, c4 = (idx & 15) << 2;
      float4 v = *reinterpret_cast<const float4*>(&Kg[(size_t)(kb + row) * DM + c4]);
      v.x = tf32r(v.x); v.y = tf32r(v.y); v.z = tf32r(v.z); v.w = tf32r(v.w);
      *reinterpret_cast<float4*>(&Ks[row][c4]) = v;
    }
    __syncthreads();

    float s[2][4][4] = {};
#pragma unroll
    for (int d8i = 0; d8i < 8; d8i++) {
      int d8 = d8i << 3;
      uint32_t bb[4][2];
#pragma unroll
      for (int nt = 0; nt < 4; nt++) {
        int cc = (wn << 5) + (nt << 3) + g;
        bb[nt][0] = __float_as_uint(Ks[cc][d8 + tig]);
        bb[nt][1] = __float_as_uint(Ks[cc][d8 + tig + 4]);
      }
#pragma unroll
      for (int mt = 0; mt < 2; mt++)
#pragma unroll
        for (int nt = 0; nt < 4; nt++)
          mma8(s[mt][nt], qa[d8i][mt], bb[nt]);
    }
#pragma unroll
    for (int mt = 0; mt < 2; mt++)
#pragma unroll
      for (int nt = 0; nt < 4; nt++) {
        rs[mt][0] += __expf(s[mt][nt][0] * INV_TEMP) + __expf(s[mt][nt][1] * INV_TEMP);
        rs[mt][1] += __expf(s[mt][nt][2] * INV_TEMP) + __expf(s[mt][nt][3] * INV_TEMP);
      }
    __syncthreads();
  }

  // Reduce rowsums across tig lanes, then across the 2 n-warps via smem
#pragma unroll
  for (int mt = 0; mt < 2; mt++)
#pragma unroll
    for (int u = 0; u < 2; u++) {
      rs[mt][u] += __shfl_xor_sync(0xffffffffu, rs[mt][u], 1);
      rs[mt][u] += __shfl_xor_sync(0xffffffffu, rs[mt][u], 2);
    }
  if (tig == 0) {
#pragma unroll
    for (int mt = 0; mt < 2; mt++)
#pragma unroll
      for (int u = 0; u < 2; u++)
        red[(wq << 5) + (mt << 4) + (u << 3) + g][wn] = rs[mt][u];
  }
  __syncthreads();
  if (tid < 128) sinv[tid] = 1.0f / (red[tid][0] + red[tid][1]);
  __syncthreads();

  float inv[2][2];
#pragma unroll
  for (int mt = 0; mt < 2; mt++) {
    inv[mt][0] = sinv[(wq << 5) + (mt << 4) + g];
    inv[mt][1] = sinv[(wq << 5) + (mt << 4) + 8 + g];
  }
  __syncthreads();   // before Es (aliasing sinv? no — Es aliases Qs; guard anyway)

  // ---------------- sweep 2: normalized attn + context ----------------
  float cx[2][4][4] = {};
  for (int kb = 0; kb < SEQ; kb += 64) {
#pragma unroll
    for (int j = 0; j < 4; j++) {
      int idx = tid + (j << 8);
      int row = idx >> 4, c4 = (idx & 15) << 2;
      float4 v = *reinterpret_cast<const float4*>(&Kg[(size_t)(kb + row) * DM + c4]);
      v.x = tf32r(v.x); v.y = tf32r(v.y); v.z = tf32r(v.z); v.w = tf32r(v.w);
      *reinterpret_cast<float4*>(&Ks[row][c4]) = v;
    }
#pragma unroll
    for (int j = 0; j < 4; j++) {
      int idx = tid + (j << 8);
      int key = idx & 63, c4 = (idx >> 6) << 2;
      float4 v = *reinterpret_cast<const float4*>(&Vg[(size_t)(kb + key) * DM + c4]);
      Vt[c4 + 0][key] = tf32r(v.x);
      Vt[c4 + 1][key] = tf32r(v.y);
      Vt[c4 + 2][key] = tf32r(v.z);
      Vt[c4 + 3][key] = tf32r(v.w);
    }
    __syncthreads();

    float s[2][4][4] = {};
#pragma unroll
    for (int d8i = 0; d8i < 8; d8i++) {
      int d8 = d8i << 3;
      uint32_t bb[4][2];
#pragma unroll
      for (int nt = 0; nt < 4; nt++) {
        int cc = (wn << 5) + (nt << 3) + g;
        bb[nt][0] = __float_as_uint(Ks[cc][d8 + tig]);
        bb[nt][1] = __float_as_uint(Ks[cc][d8 + tig + 4]);
      }
#pragma unroll
      for (int mt = 0; mt < 2; mt++)
#pragma unroll
        for (int nt = 0; nt < 4; nt++)
          mma8(s[mt][nt], qa[d8i][mt], bb[nt]);
    }

    // exp, normalize, write gmem (float2) + smem Es (float2)
#pragma unroll
    for (int mt = 0; mt < 2; mt++) {
      int r0 = (wq << 5) + (mt << 4) + g;
#pragma unroll
      for (int nt = 0; nt < 4; nt++) {
        int c0 = (wn << 5) + (nt << 3) + (tig << 1);
        float e0 = __expf(s[mt][nt][0] * INV_TEMP) * inv[mt][0];
        float e1 = __expf(s[mt][nt][1] * INV_TEMP) * inv[mt][0];
        float e2 = __expf(s[mt][nt][2] * INV_TEMP) * inv[mt][1];
        float e3 = __expf(s[mt][nt][3] * INV_TEMP) * inv[mt][1];
        size_t go = ((size_t)bh * SEQ + qbase + r0) * SEQ + kb + c0;
        float2 w0 = {e0, e1}, w1 = {e2, e3};
        *reinterpret_cast<float2*>(&attn_out[go]) = w0;
        *reinterpret_cast<float2*>(&attn_out[go + (size_t)8 * SEQ]) = w1;
        float2 t0 = {tf32r(e0), tf32r(e1)}, t1 = {tf32r(e2), tf32r(e3)};
        *reinterpret_cast<float2*>(&Es[r0][c0]) = t0;
        *reinterpret_cast<float2*>(&Es[r0 + 8][c0]) = t1;
      }
    }
    __syncthreads();

    // ctx += E @ V  (m=q, n=dv, k=key)
#pragma unroll
    for (int k8 = 0; k8 < 64; k8 += 8) {
      uint32_t a[2][4], bb[4][2];
#pragma unroll
      for (int mt = 0; mt < 2; mt++) {
        int r = (wq << 5) + (mt << 4) + g;
        a[mt][0] = __float_as_uint(Es[r][k8 + tig]);
        a[mt][1] = __float_as_uint(Es[r + 8][k8 + tig]);
        a[mt][2] = __float_as_uint(Es[r][k8 + tig + 4]);
        a[mt][3] = __float_as_uint(Es[r + 8][k8 + tig + 4]);
      }
#pragma unroll
      for (int nt = 0; nt < 4; nt++) {
        int cc = (wn << 5) + (nt << 3) + g;
        bb[nt][0] = __float_as_uint(Vt[cc][k8 + tig]);
        bb[nt][1] = __float_as_uint(Vt[cc][k8 + tig + 4]);
      }
#pragma unroll
      for (int mt = 0; mt < 2; mt++)
#pragma unroll
        for (int nt = 0; nt < 4; nt++)
          mma8(cx[mt][nt], a[mt], bb[nt]);
    }
    __syncthreads();
  }

  // Write context (merged heads layout), already normalized
#pragma unroll
  for (int mt = 0; mt < 2; mt++) {
    int r = b * SEQ + qbase + (wq << 5) + (mt << 4) + g;
#pragma unroll
    for (int nt = 0; nt < 4; nt++) {
      int cc = h * DKH + (wn << 5) + (nt << 3) + (tig << 1);
      float2 w0 = {cx[mt][nt][0], cx[mt][nt][1]};
      float2 w1 = {cx[mt][nt][2], cx[mt][nt][3]};
      *reinterpret_cast<float2*>(&g_ctx[(size_t)r * DM + cc]) = w0;
      *reinterpret_cast<float2*>(&g_ctx[(size_t)(r + 8) * DM + cc]) = w1;
    }
  }
}

// ---------------------------------------------------------------------------
// LayerNorm over last dim (512), one block per row.
// ---------------------------------------------------------------------------
__global__ __launch_bounds__(256) void ln_kernel(
    const float* __restrict__ gamma, const float* __restrict__ beta,
    float* __restrict__ y) {
  __shared__ float warp_s[8], warp_q[8];
  __shared__ float s_mu, s_rstd;
  const int row = blockIdx.x;
  const int tid = threadIdx.x;
  const float* x = g_x + (size_t)row * DM;

  float v0 = x[tid], v1 = x[tid + 256];
  float s = v0 + v1;
  float q = v0 * v0 + v1 * v1;
#pragma unroll
  for (int o = 16; o > 0; o >>= 1) {
    s += __shfl_xor_sync(0xffffffffu, s, o);
    q += __shfl_xor_sync(0xffffffffu, q, o);
  }
  if ((tid & 31) == 0) { warp_s[tid >> 5] = s; warp_q[tid >> 5] = q; }
  __syncthreads();
  if (tid == 0) {
    float ss = 0.f, qq = 0.f;
#pragma unroll
    for (int i = 0; i < 8; i++) { ss += warp_s[i]; qq += warp_q[i]; }
    float mu = ss * (1.0f / DM);
    float var = qq * (1.0f / DM) - mu * mu;
    s_mu = mu;
    s_rstd = rsqrtf(var + LN_EPS);
  }
  __syncthreads();
  float mu = s_mu, r = s_rstd;
  y[(size_t)row * DM + tid]       = (v0 - mu) * r * gamma[tid] + beta[tid];
  y[(size_t)row * DM + tid + 256] = (v1 - mu) * r * gamma[tid + 256] + beta[tid + 256];
}

// ---------------------------------------------------------------------------
extern "C" void kernel_launch(void* const* d_in, const int* in_sizes, int n_in,
                              void* d_out, int out_size) {
  const float* q     = (const float*)d_in[0];
  const float* k     = (const float*)d_in[1];
  const float* v     = (const float*)d_in[2];
  const float* Wq    = (const float*)d_in[3];
  const float* bq    = (const float*)d_in[4];
  const float* Wk    = (const float*)d_in[5];
  const float* bk    = (const float*)d_in[6];
  const float* Wv    = (const float*)d_in[7];
  const float* bv    = (const float*)d_in[8];
  const float* Wfc   = (const float*)d_in[9];
  const float* bfc   = (const float*)d_in[10];
  const float* gamma = (const float*)d_in[11];
  const float* beta  = (const float*)d_in[12];

  float* out = (float*)d_out;                       // y: [2,2048,512]
  float* attn_out = out + (size_t)MM * DM;          // attn: [16,2048,2048]

  float *gQ, *gK, *gV, *gctx, *gx;
  cudaGetSymbolAddress((void**)&gQ, g_Q);
  cudaGetSymbolAddress((void**)&gK, g_K);
  cudaGetSymbolAddress((void**)&gV, g_V);
  cudaGetSymbolAddress((void**)&gctx, g_ctx);
  cudaGetSymbolAddress((void**)&gx, g_x);

  cudaFuncSetAttribute(attn_mma, cudaFuncAttributeMaxDynamicSharedMemorySize, 71168);

  dim3 gg(DM / 128, MM / 128);     // (4, 32) = 128 CTAs
  gemm_mma<<<gg, 256>>>(q, Wq, bq, nullptr, gQ);
  gemm_mma<<<gg, 256>>>(k, Wk, bk, nullptr, gK);
  gemm_mma<<<gg, 256>>>(v, Wv, bv, nullptr, gV);

  dim3 ga(SEQ / 128, NH * B2);     // (16, 16)
  attn_mma<<<ga, 256, 71168>>>(attn_out);

  gemm_mma<<<gg, 256>>>(gctx, Wfc, bfc, q, gx);
  ln_kernel<<<MM, 256>>>(gamma, beta, out);
}